// round 16
// baseline (speedup 1.0000x reference)
#include <cuda_runtime.h>

#define NB      32
#define NIN     1034
#define NOUT    512
#define STRIDE  1088
#define KNS     1000.0f
#define MINW    (-0.3678794411714423f)
#define EF      2.718281828459045f
#define NBUCK   2048
#define GROUP   16
#define ITILES  33          // ceil(1034/32)
#define OTILES  16          // 512/32

// packed per-batch sorted data: (t, e^t, t*e^t, (idx*512)-as-int-bits)
__device__ float4 g_pack[NB * STRIDE];
// transposed weights: Wt[i][o], 1034 x 512
__device__ float  g_wt[NIN * NOUT];

__device__ __forceinline__ float get_t(const float* __restrict__ x,
                                       const float* __restrict__ pulse,
                                       int b, int i) {
    return (i < 1024) ? x[b * 1024 + i] : pulse[i - 1024];
}

__device__ __forceinline__ int bucket_of(float t) {
    int bid = (int)(t * (float)NBUCK);
    return bid < 0 ? 0 : (bid >= NBUCK ? NBUCK - 1 : bid);
}

// ---------------------------------------------------------------------------
// Kernel 1 (fused): blocks 0..31 -> per-batch bucket sort + pack;
//                   blocks 32..559 -> 32x32 transpose tiles of W.
// ---------------------------------------------------------------------------
__global__ void prep_kernel(const float* __restrict__ x,
                            const float* __restrict__ pulse,
                            const float* __restrict__ W) {
    __shared__ int cnt [NBUCK];
    __shared__ int base[NBUCK];
    __shared__ unsigned long long keys[NIN];
    __shared__ float wsum[32];
    __shared__ float tile[32][33];

    const int bid = blockIdx.x;
    const int tid = threadIdx.x;

    if (bid >= NB) {
        const int tb = bid - NB;
        const int i0 = (tb % ITILES) * 32;
        const int o0 = (tb / ITILES) * 32;
        const int tx = tid & 31, ty = tid >> 5;
        const int i = i0 + tx;
        if (i < NIN) tile[ty][tx] = W[(o0 + ty) * NIN + i];
        __syncthreads();
        const int i2 = i0 + ty;
        if (i2 < NIN) g_wt[i2 * NOUT + o0 + tx] = tile[tx][ty];
        return;
    }

    const int b = bid;
    const int lane = tid & 31, wid = tid >> 5;

    cnt[tid] = 0; cnt[tid + 1024] = 0;
    __syncthreads();

    for (int i = tid; i < NIN; i += 1024) {
        const float t = get_t(x, pulse, b, i);
        atomicAdd(&cnt[bucket_of(t)], 1);
    }
    __syncthreads();

    {
        const int v0 = cnt[2 * tid], v1 = cnt[2 * tid + 1];
        float s = (float)(v0 + v1);
        #pragma unroll
        for (int off = 1; off < 32; off <<= 1) {
            const float u = __shfl_up_sync(0xffffffffu, s, off);
            if (lane >= off) s += u;
        }
        if (lane == 31) wsum[wid] = s;
        __syncthreads();
        if (wid == 0) {
            float ws = wsum[lane];
            #pragma unroll
            for (int off = 1; off < 32; off <<= 1) {
                const float u = __shfl_up_sync(0xffffffffu, ws, off);
                if (lane >= off) ws += u;
            }
            wsum[lane] = ws;
        }
        __syncthreads();
        const int incl = (int)s + (wid ? (int)wsum[wid - 1] : 0);
        const int excl = incl - v0 - v1;
        base[2 * tid]     = excl;
        base[2 * tid + 1] = excl + v0;
        __syncthreads();
        cnt[2 * tid]     = excl;
        cnt[2 * tid + 1] = excl + v0;
    }
    __syncthreads();

    for (int i = tid; i < NIN; i += 1024) {
        const float t = get_t(x, pulse, b, i);
        const int pos = atomicAdd(&cnt[bucket_of(t)], 1);
        keys[pos] = ((unsigned long long)__float_as_uint(t) << 32) | (unsigned)i;
    }
    __syncthreads();

    for (int bk = tid; bk < NBUCK; bk += 1024) {
        const int s0 = base[bk];
        const int s1 = (bk + 1 < NBUCK) ? base[bk + 1] : NIN;
        for (int i = s0 + 1; i < s1; ++i) {
            const unsigned long long v = keys[i];
            int j = i - 1;
            while (j >= s0 && keys[j] > v) { keys[j + 1] = keys[j]; --j; }
            keys[j + 1] = v;
        }
    }
    __syncthreads();

    for (int i = tid; i < STRIDE; i += 1024) {
        if (i < NIN) {
            const unsigned long long v = keys[i];
            const float t = __uint_as_float((unsigned)(v >> 32));
            const int idx = (int)(unsigned)v;
            const float z = expf(t);
            // store idx*NOUT pre-scaled for the solve kernel
            g_pack[b * STRIDE + i] = make_float4(t, z, z * t,
                                                 __int_as_float(idx << 9));
        } else {
            g_pack[b * STRIDE + i] = make_float4(KNS, 0.0f, 0.0f,
                                                 __int_as_float(0));
        }
    }
}

// ---------------------------------------------------------------------------
// Kernel 2: one THREAD per (batch, output); 32-thread blocks (1 warp).
// pk in smem. Depth-2 weight prefetch via zero-mov ping-pong phases.
// Per group of 16: accumulate-only FMA chain + ONE coarse test; exact
// per-element replay only on the firing group. One Lambert at the end.
// ---------------------------------------------------------------------------
__device__ __forceinline__ void solve_group(
    const float4* __restrict__ spk, const float* __restrict__ w,
    int k0, float& A, float& Bv, float& fA, float& fB, bool& found)
{
    const float A0 = A, B0 = Bv;
    #pragma unroll
    for (int j = 0; j < GROUP; ++j) {
        const float4 p = spk[k0 + j];
        A  = fmaf(w[j], p.y, A);
        Bv = fmaf(w[j], p.z, Bv);
    }
    const float4 q = spk[k0 + GROUP];
    bool coarse = false;
    if (!found && A > 1e-10f) {
        const float lnA = __logf(A);
        coarse = (fmaf(A, lnA - 1.0f, -Bv) >= 0.0f)
              && ((q.x >= lnA) || (fmaf(A, q.x, -Bv) >= q.y));
    }
    if (coarse) {
        float Ar = A0, Br = B0;
        #pragma unroll
        for (int j = 0; j < GROUP; ++j) {
            const float4 p = spk[k0 + j];
            Ar = fmaf(w[j], p.y, Ar);
            Br = fmaf(w[j], p.z, Br);
            const float tn = (j < GROUP - 1) ? spk[k0 + j + 1].x : q.x;
            const float zn = (j < GROUP - 1) ? spk[k0 + j + 1].y : q.y;
            const float lnA = __logf(Ar);
            const bool valid =
                   (Ar > 1e-10f)
                && (fmaf(Ar, lnA - 1.0f, -Br) >= 0.0f)
                && (fmaf(Ar, p.x, -Br) <= p.y)
                && ((tn >= lnA) || (fmaf(Ar, tn, -Br) >= zn))
                && (p.x < KNS);
            const bool take = valid && !found;
            fA = take ? Ar : fA;
            fB = take ? Br : fB;
            found |= valid;
        }
    }
}

__global__ void __launch_bounds__(32)
solve_kernel(float* __restrict__ out) {
    __shared__ float4 spk[STRIDE];

    const int tid = threadIdx.x;
    const int gt  = blockIdx.x * 32 + tid;
    const int b   = gt >> 9;
    const int o   = gt & 511;

    {   // stage this batch row's packed data (coalesced)
        const float4* __restrict__ pk = g_pack + b * STRIDE;
        #pragma unroll 4
        for (int i = tid; i < STRIDE; i += 32) spk[i] = pk[i];
    }
    __syncthreads();

    const float* __restrict__ wt = g_wt;

    float A = 0.0f, Bv = 0.0f;
    float fA = 1.0f, fB = 0.0f;
    bool  found = false;

    // prime: weights for groups 0 and 1 (pk.w holds idx*512)
    float w0[GROUP], w1[GROUP];
    #pragma unroll
    for (int j = 0; j < GROUP; ++j)
        w0[j] = wt[__float_as_int(spk[j].w) + o];
    #pragma unroll
    for (int j = 0; j < GROUP; ++j)
        w1[j] = wt[__float_as_int(spk[GROUP + j].w) + o];

    for (int k0 = 0; k0 < NIN; k0 += 2 * GROUP) {
        // phase A: compute group k0 with w0, then reload w0 <- group k0+2G
        solve_group(spk, w0, k0, A, Bv, fA, fB, found);
        #pragma unroll
        for (int j = 0; j < GROUP; ++j)
            w0[j] = wt[__float_as_int(spk[k0 + 2 * GROUP + j].w) + o];

        // phase B: compute group k0+G with w1, then reload w1 <- group k0+3G
        solve_group(spk, w1, k0 + GROUP, A, Bv, fA, fB, found);
        if (__all_sync(0xffffffffu, found)) break;
        #pragma unroll
        for (int j = 0; j < GROUP; ++j)
            w1[j] = wt[__float_as_int(spk[k0 + 3 * GROUP + j].w) + o];
    }

    // one Lambert solve per thread
    float tc = KNS;
    if (found) {
        const float boa = fB / fA;
        float xw = -1.0f / fA * expf(fminf(boa, 80.0f));
        xw = fmaxf(fminf(xw, 0.0f), MINW);
        float wv;
        if (xw < -0.25f) {
            const float pbr = sqrtf(fmaxf(2.0f * (1.0f + EF * xw), 0.0f));
            wv = -1.0f + pbr * (1.0f + pbr * (-0.33333333f + pbr * 0.15277778f));
        } else {
            wv = xw * (1.0f - xw * (1.0f - 1.5f * xw));
        }
        #pragma unroll
        for (int it = 0; it < 3; ++it) {
            const float ew = expf(wv);
            const float f  = wv * ew - xw;
            const float denom = ew * (wv + 1.0f)
                      - (wv + 2.0f) * f / (2.0f * (wv + 1.0f) + 1e-12f);
            wv = wv - f / (denom + 1e-12f);
        }
        tc = boa - wv;
    }
    out[b * NOUT + o] = tc;
}

// ---------------------------------------------------------------------------
extern "C" void kernel_launch(void* const* d_in, const int* in_sizes, int n_in,
                              void* d_out, int out_size) {
    const float* x      = (const float*)d_in[0];   // [32, 1024]
    const float* weight = (const float*)d_in[1];   // [512, 1034]
    const float* pulse  = (const float*)d_in[2];   // [10]
    float* out = (float*)d_out;                    // [32, 512]

    prep_kernel<<<NB + ITILES * OTILES, 1024>>>(x, pulse, weight);

    // one thread per (b,o); 1-warp blocks for finest load balance
    solve_kernel<<<(NB * NOUT) / 32, 32>>>(out);
}

// round 17
// speedup vs baseline: 1.3401x; 1.3401x over previous
#include <cuda_runtime.h>

#define NB      32
#define NIN     1034
#define NOUT    512
#define STRIDE  1152       // padded: lookahead reads up to spk[1151]
#define KNS     1000.0f
#define MINW    (-0.3678794411714423f)
#define EF      2.718281828459045f
#define NBUCK   2048
#define SEG     16         // elements per quad-lane segment
#define ITILES  33
#define OTILES  16

// packed per-batch sorted data: (t, e^t, t*e^t, (idx*512)-as-int-bits)
__device__ float4 g_pack[NB * STRIDE];
// transposed weights: Wt[i][o], 1034 x 512
__device__ float  g_wt[NIN * NOUT];

__device__ __forceinline__ float get_t(const float* __restrict__ x,
                                       const float* __restrict__ pulse,
                                       int b, int i) {
    return (i < 1024) ? x[b * 1024 + i] : pulse[i - 1024];
}

__device__ __forceinline__ int bucket_of(float t) {
    int bid = (int)(t * (float)NBUCK);
    return bid < 0 ? 0 : (bid >= NBUCK ? NBUCK - 1 : bid);
}

__device__ __forceinline__ unsigned long long pack2(float lo, float hi) {
    unsigned long long r;
    asm("mov.b64 %0, {%1, %2};" : "=l"(r) : "f"(lo), "f"(hi));
    return r;
}
__device__ __forceinline__ void unpack2(unsigned long long v, float& lo, float& hi) {
    asm("mov.b64 {%0, %1}, %2;" : "=f"(lo), "=f"(hi) : "l"(v));
}
__device__ __forceinline__ unsigned long long addf32x2(unsigned long long a,
                                                       unsigned long long b) {
    unsigned long long r;
    asm("add.rn.f32x2 %0, %1, %2;" : "=l"(r) : "l"(a), "l"(b));
    return r;
}

// ---------------------------------------------------------------------------
// Kernel 1 (fused): blocks 0..31 sort+pack; blocks 32..559 transpose W.
// ---------------------------------------------------------------------------
__global__ void prep_kernel(const float* __restrict__ x,
                            const float* __restrict__ pulse,
                            const float* __restrict__ W) {
    __shared__ int cnt [NBUCK];
    __shared__ int base[NBUCK];
    __shared__ unsigned long long keys[NIN];
    __shared__ float wsum[32];
    __shared__ float tile[32][33];

    const int bid = blockIdx.x;
    const int tid = threadIdx.x;

    if (bid >= NB) {
        const int tb = bid - NB;
        const int i0 = (tb % ITILES) * 32;
        const int o0 = (tb / ITILES) * 32;
        const int tx = tid & 31, ty = tid >> 5;
        const int i = i0 + tx;
        if (i < NIN) tile[ty][tx] = W[(o0 + ty) * NIN + i];
        __syncthreads();
        const int i2 = i0 + ty;
        if (i2 < NIN) g_wt[i2 * NOUT + o0 + tx] = tile[tx][ty];
        return;
    }

    const int b = bid;
    const int lane = tid & 31, wid = tid >> 5;

    cnt[tid] = 0; cnt[tid + 1024] = 0;
    __syncthreads();

    for (int i = tid; i < NIN; i += 1024) {
        const float t = get_t(x, pulse, b, i);
        atomicAdd(&cnt[bucket_of(t)], 1);
    }
    __syncthreads();

    {
        const int v0 = cnt[2 * tid], v1 = cnt[2 * tid + 1];
        float s = (float)(v0 + v1);
        #pragma unroll
        for (int off = 1; off < 32; off <<= 1) {
            const float u = __shfl_up_sync(0xffffffffu, s, off);
            if (lane >= off) s += u;
        }
        if (lane == 31) wsum[wid] = s;
        __syncthreads();
        if (wid == 0) {
            float ws = wsum[lane];
            #pragma unroll
            for (int off = 1; off < 32; off <<= 1) {
                const float u = __shfl_up_sync(0xffffffffu, ws, off);
                if (lane >= off) ws += u;
            }
            wsum[lane] = ws;
        }
        __syncthreads();
        const int incl = (int)s + (wid ? (int)wsum[wid - 1] : 0);
        const int excl = incl - v0 - v1;
        base[2 * tid]     = excl;
        base[2 * tid + 1] = excl + v0;
        __syncthreads();
        cnt[2 * tid]     = excl;
        cnt[2 * tid + 1] = excl + v0;
    }
    __syncthreads();

    for (int i = tid; i < NIN; i += 1024) {
        const float t = get_t(x, pulse, b, i);
        const int pos = atomicAdd(&cnt[bucket_of(t)], 1);
        keys[pos] = ((unsigned long long)__float_as_uint(t) << 32) | (unsigned)i;
    }
    __syncthreads();

    for (int bk = tid; bk < NBUCK; bk += 1024) {
        const int s0 = base[bk];
        const int s1 = (bk + 1 < NBUCK) ? base[bk + 1] : NIN;
        for (int i = s0 + 1; i < s1; ++i) {
            const unsigned long long v = keys[i];
            int j = i - 1;
            while (j >= s0 && keys[j] > v) { keys[j + 1] = keys[j]; --j; }
            keys[j + 1] = v;
        }
    }
    __syncthreads();

    for (int i = tid; i < STRIDE; i += 1024) {
        if (i < NIN) {
            const unsigned long long v = keys[i];
            const float t = __uint_as_float((unsigned)(v >> 32));
            const int idx = (int)(unsigned)v;
            const float z = expf(t);
            g_pack[b * STRIDE + i] = make_float4(t, z, z * t,
                                                 __int_as_float(idx << 9));
        } else {
            g_pack[b * STRIDE + i] = make_float4(KNS, 0.0f, 0.0f,
                                                 __int_as_float(0));
        }
    }
}

// ---------------------------------------------------------------------------
// Kernel 2: FOUR threads (a quad) per (batch, output). Each iteration covers
// 64 sorted elements: quad-lane ql owns segment [k0+16*ql, +16). Segment
// sums in parallel, packed quad-scan for prefixes, coarse test per segment
// end, exact per-element replay only on firing segments, quad-min winner.
// ---------------------------------------------------------------------------
__global__ void __launch_bounds__(64)
solve_kernel(float* __restrict__ out) {
    __shared__ float4 spk[STRIDE];

    const int tid  = threadIdx.x;
    const int lane = tid & 31;
    const int ql   = lane & 3;                     // quad lane = segment slot
    const int b    = blockIdx.x >> 5;              // 32 blocks per batch row
    const int o    = (blockIdx.x & 31) * 16 + (tid >> 2);
    const int qbase = lane & ~3;                   // quad's base lane in warp

    {   // stage this batch row's packed data (coalesced)
        const float4* __restrict__ pk = g_pack + b * STRIDE;
        #pragma unroll
        for (int i = tid; i < STRIDE; i += 64) spk[i] = pk[i];
    }
    __syncthreads();

    const float* __restrict__ wt = g_wt;
    const int sb0 = SEG * ql;                      // segment offset in window

    unsigned long long carry = pack2(0.0f, 0.0f);
    float fA = 1.0f, fB = 0.0f;
    bool  found = false;

    // prime: weights for window 0's own segment (pk.w holds idx*512)
    float w[SEG], wn[SEG];
    #pragma unroll
    for (int j = 0; j < SEG; ++j)
        w[j] = wt[__float_as_int(spk[sb0 + j].w) + o];

    for (int k0 = 0; k0 < NIN; k0 += 4 * SEG) {
        const int sb = k0 + sb0;

        // prefetch next window's weights (idx via fast LDS; pads -> row 0)
        #pragma unroll
        for (int j = 0; j < SEG; ++j)
            wn[j] = wt[__float_as_int(spk[sb + 4 * SEG + j].w) + o];

        // segment sums (parallel across quad)
        float sA = 0.0f, sB = 0.0f;
        #pragma unroll
        for (int j = 0; j < SEG; ++j) {
            const float4 p = spk[sb + j];
            sA = fmaf(w[j], p.y, sA);
            sB = fmaf(w[j], p.z, sB);
        }
        const unsigned long long own = pack2(sA, sB);

        // inclusive quad scan (2 packed shfl steps, quad-guarded)
        unsigned long long inc = own;
        {
            const unsigned long long u1 = __shfl_up_sync(0xffffffffu, inc, 1);
            if (ql >= 1) inc = addf32x2(inc, u1);
            const unsigned long long u2 = __shfl_up_sync(0xffffffffu, inc, 2);
            if (ql >= 2) inc = addf32x2(inc, u2);
        }
        const unsigned long long exs = __shfl_up_sync(0xffffffffu, inc, 1);
        const unsigned long long prefix = (ql == 0) ? carry
                                                    : addf32x2(carry, exs);
        const unsigned long long endAB = addf32x2(prefix, own);
        const unsigned long long tot = __shfl_sync(0xffffffffu, inc, qbase + 3);

        // coarse "exists valid k <= segment end" test
        bool lf = false;
        float lfA = 1.0f, lfB = 0.0f;
        if (!found) {
            float A, Bv;
            unpack2(endAB, A, Bv);
            bool coarse = false;
            if (A > 1e-10f) {
                const float4 q = spk[sb + SEG];
                const float lnA = __logf(A);
                coarse = (fmaf(A, lnA - 1.0f, -Bv) >= 0.0f)
                      && ((q.x >= lnA) || (fmaf(A, q.x, -Bv) >= q.y));
            }
            if (coarse) {
                // exact per-element replay of this segment from its prefix
                float Ar, Br;
                unpack2(prefix, Ar, Br);
                #pragma unroll
                for (int j = 0; j < SEG; ++j) {
                    const float4 p = spk[sb + j];
                    Ar = fmaf(w[j], p.y, Ar);
                    Br = fmaf(w[j], p.z, Br);
                    const float4 pn = spk[sb + j + 1];
                    const float lnA = __logf(Ar);
                    const bool valid =
                           (Ar > 1e-10f)
                        && (fmaf(Ar, lnA - 1.0f, -Br) >= 0.0f)
                        && (fmaf(Ar, p.x, -Br) <= p.y)
                        && ((pn.x >= lnA) || (fmaf(Ar, pn.x, -Br) >= pn.y))
                        && (p.x < KNS);
                    const bool take = valid && !lf;
                    lfA = take ? Ar : lfA;
                    lfB = take ? Br : lfB;
                    lf |= valid;
                }
            }
        }

        // pick first-firing segment within the quad
        const unsigned bal = __ballot_sync(0xffffffffu, lf);
        const unsigned nib = (bal >> qbase) & 0xFu;
        if (nib && !found) {
            const int src = qbase + (__ffs((int)nib) - 1);
            fA = __shfl_sync(0xffffffffu, lfA, src);
            fB = __shfl_sync(0xffffffffu, lfB, src);
            found = true;
        }
        // NOTE: lanes not in `if` still executed the shfl above? keep uniform:
        // (the shfl is inside the branch; make it unconditional instead)

        carry = addf32x2(carry, tot);

        if (__all_sync(0xffffffffu, found)) break;

        #pragma unroll
        for (int j = 0; j < SEG; ++j) w[j] = wn[j];
    }

    // one Lambert solve per pair, on quad-lane 0
    if (ql == 0) {
        float tc = KNS;
        if (found) {
            const float boa = fB / fA;
            float xw = -1.0f / fA * expf(fminf(boa, 80.0f));
            xw = fmaxf(fminf(xw, 0.0f), MINW);
            float wv;
            if (xw < -0.25f) {
                const float pbr = sqrtf(fmaxf(2.0f * (1.0f + EF * xw), 0.0f));
                wv = -1.0f + pbr * (1.0f + pbr * (-0.33333333f + pbr * 0.15277778f));
            } else {
                wv = xw * (1.0f - xw * (1.0f - 1.5f * xw));
            }
            #pragma unroll
            for (int it = 0; it < 3; ++it) {
                const float ew = expf(wv);
                const float f  = wv * ew - xw;
                const float denom = ew * (wv + 1.0f)
                          - (wv + 2.0f) * f / (2.0f * (wv + 1.0f) + 1e-12f);
                wv = wv - f / (denom + 1e-12f);
            }
            tc = boa - wv;
        }
        out[b * NOUT + o] = tc;
    }
}

// ---------------------------------------------------------------------------
extern "C" void kernel_launch(void* const* d_in, const int* in_sizes, int n_in,
                              void* d_out, int out_size) {
    const float* x      = (const float*)d_in[0];   // [32, 1024]
    const float* weight = (const float*)d_in[1];   // [512, 1034]
    const float* pulse  = (const float*)d_in[2];   // [10]
    float* out = (float*)d_out;                    // [32, 512]

    prep_kernel<<<NB + ITILES * OTILES, 1024>>>(x, pulse, weight);

    // quad (4 threads) per (b,o): 65536 threads, 64-thr blocks -> 1024 blocks
    solve_kernel<<<(NB * NOUT * 4) / 64, 64>>>(out);
}